// round 1
// baseline (speedup 1.0000x reference)
#include <cuda_runtime.h>
#include <math.h>

#define J 20
#define CONST_PER_J 57
// layout per joint: M0[9]@0, M1[9]@9, M2[9]@18, p_rev[3]@27,
//                   Rpri[9]@30, v_pri[3]@39, p_pri[3]@42, Rtrk[9]@45, p_trk[3]@54

__device__ float g_jc[J * CONST_PER_J];

__device__ __forceinline__ void rpy2r_dev(float r, float p, float y, float* R) {
    float cr = cosf(r), sr = sinf(r);
    float cp = cosf(p), sp = sinf(p);
    float cy = cosf(y), sy = sinf(y);
    R[0] = cy * cp; R[1] = cy * sp * sr - sy * cr; R[2] = cy * sp * cr + sy * sr;
    R[3] = sy * cp; R[4] = sy * sp * sr + cy * cr; R[5] = sy * sp * cr - cy * sr;
    R[6] = -sp;     R[7] = cp * sr;                R[8] = cp * cr;
}

__device__ __forceinline__ void mm3(float* D, const float* A, const float* B) {
#pragma unroll
    for (int r = 0; r < 3; r++)
#pragma unroll
        for (int c = 0; c < 3; c++)
            D[r * 3 + c] = fmaf(A[r * 3 + 0], B[0 * 3 + c],
                           fmaf(A[r * 3 + 1], B[1 * 3 + c],
                                A[r * 3 + 2] * B[2 * 3 + c]));
}

// Precompute per-joint constant fold. One block, threads 0..19.
__global__ void prep_kernel(const float* __restrict__ rev_p_off,
                            const float* __restrict__ rev_rpy_off,
                            const float* __restrict__ pri_p_off,
                            const float* __restrict__ pri_rpy_off,
                            const float* __restrict__ rev_axis,
                            const float* __restrict__ pri_axis,
                            const float* __restrict__ p_track,
                            const float* __restrict__ rpy_track) {
    int j = threadIdx.x;
    if (j >= J) return;
    float* C = g_jc + j * CONST_PER_J;

    // revolute offset rotation
    float Ro[9];
    rpy2r_dev(rev_rpy_off[j * 3 + 0], rev_rpy_off[j * 3 + 1], rev_rpy_off[j * 3 + 2], Ro);

    // normalized axis -> K, K^2
    float ax = rev_axis[j * 3 + 0], ay = rev_axis[j * 3 + 1], az = rev_axis[j * 3 + 2];
    float n = sqrtf(ax * ax + ay * ay + az * az) + 1e-12f;
    ax /= n; ay /= n; az /= n;
    float K[9]  = {0.f, -az, ay,  az, 0.f, -ax,  -ay, ax, 0.f};
    float K2[9];
    mm3(K2, K, K);

    float M1[9], M2[9];
    mm3(M1, Ro, K);
    mm3(M2, Ro, K2);
#pragma unroll
    for (int i = 0; i < 9; i++) { C[i] = Ro[i]; C[9 + i] = M1[i]; C[18 + i] = M2[i]; }
    C[27] = rev_p_off[j * 3 + 0]; C[28] = rev_p_off[j * 3 + 1]; C[29] = rev_p_off[j * 3 + 2];

    // prismatic
    float Rp[9];
    rpy2r_dev(pri_rpy_off[j * 3 + 0], pri_rpy_off[j * 3 + 1], pri_rpy_off[j * 3 + 2], Rp);
#pragma unroll
    for (int i = 0; i < 9; i++) C[30 + i] = Rp[i];
    float pax = pri_axis[j * 3 + 0], pay = pri_axis[j * 3 + 1], paz = pri_axis[j * 3 + 2];
#pragma unroll
    for (int r = 0; r < 3; r++)
        C[39 + r] = Rp[r * 3 + 0] * pax + Rp[r * 3 + 1] * pay + Rp[r * 3 + 2] * paz;
    C[42] = pri_p_off[j * 3 + 0]; C[43] = pri_p_off[j * 3 + 1]; C[44] = pri_p_off[j * 3 + 2];

    // tracking
    float Rt[9];
    rpy2r_dev(rpy_track[j * 3 + 0], rpy_track[j * 3 + 1], rpy_track[j * 3 + 2], Rt);
#pragma unroll
    for (int i = 0; i < 9; i++) C[45 + i] = Rt[i];
    C[54] = p_track[j * 3 + 0]; C[55] = p_track[j * 3 + 1]; C[56] = p_track[j * 3 + 2];
}

// Stage one 4x4 (12 meaningful floats) per lane in warp smem, drain coalesced.
__device__ __forceinline__ void emit_mat(float* stg, int lane, int wb0,
                                         float* __restrict__ tbase, int nMat, int slot,
                                         const float* R, const float* p) {
    float4* sp = (float4*)(stg + lane * 12);
    sp[0] = make_float4(R[0], R[1], R[2], p[0]);
    sp[1] = make_float4(R[3], R[4], R[5], p[1]);
    sp[2] = make_float4(R[6], R[7], R[8], p[2]);
    __syncwarp();
#pragma unroll
    for (int k = 0; k < 4; k++) {
        int c  = k * 32 + lane;   // 0..127: 32 rows x 4 quads
        int bl = c >> 2;
        int m  = c & 3;
        float4 v;
        if (m < 3) v = *(const float4*)(stg + bl * 12 + 4 * m);
        else       v = make_float4(0.f, 0.f, 0.f, 1.f);
        *(float4*)(tbase + ((size_t)(wb0 + bl) * nMat + slot) * 16 + 4 * m) = v;
    }
    __syncwarp();
}

__global__ void __launch_bounds__(128, 1)
fk_kernel(const float* __restrict__ rev_q, const float* __restrict__ pri_q,
          float* __restrict__ out, int B) {
    __shared__ float sC[J * CONST_PER_J];
    __shared__ float sStage[4][32 * 12];

    int tid = threadIdx.x;
    for (int i = tid; i < J * CONST_PER_J; i += 128) sC[i] = g_jc[i];
    __syncthreads();

    int b    = blockIdx.x * 128 + tid;
    int lane = tid & 31;
    int w    = tid >> 5;
    int wb0  = blockIdx.x * 128 + w * 32;
    float* stg = sStage[w];

    float* outTrk = out;
    float* outRev = out + (size_t)B * 160;   // B*10*16
    float* outPri = out + (size_t)B * 480;   // + B*20*16

    float R[9] = {1.f, 0.f, 0.f, 0.f, 1.f, 0.f, 0.f, 0.f, 1.f};
    float p[3] = {0.f, 0.f, 0.f};

#pragma unroll
    for (int j = 0; j < J; j++) {
        const float* C = sC + j * CONST_PER_J;

        float q = __ldg(&rev_q[(size_t)b * J + j]);
        float s, c;
        sincosf(q, &s, &c);
        float ic = 1.f - c;

        // R_step = M0 + s*M1 + (1-c)*M2
        float Rs[9];
#pragma unroll
        for (int i = 0; i < 9; i++)
            Rs[i] = fmaf(s, C[9 + i], fmaf(ic, C[18 + i], C[i]));

        // out1 = out @ rev_step
        float R1[9], p1[3];
        mm3(R1, R, Rs);
#pragma unroll
        for (int r = 0; r < 3; r++)
            p1[r] = fmaf(R[r * 3 + 0], C[27],
                    fmaf(R[r * 3 + 1], C[28],
                    fmaf(R[r * 3 + 2], C[29], p[r])));
        emit_mat(stg, lane, wb0, outRev, J, j, R1, p1);

        // out2 = out1 @ pri_step
        float qp = __ldg(&pri_q[(size_t)b * J + j]);
        float ps0 = fmaf(qp, C[39], C[42]);
        float ps1 = fmaf(qp, C[40], C[43]);
        float ps2 = fmaf(qp, C[41], C[44]);
        float R2[9], p2[3];
        mm3(R2, R1, C + 30);
#pragma unroll
        for (int r = 0; r < 3; r++)
            p2[r] = fmaf(R1[r * 3 + 0], ps0,
                    fmaf(R1[r * 3 + 1], ps1,
                    fmaf(R1[r * 3 + 2], ps2, p1[r])));
        emit_mat(stg, lane, wb0, outPri, J, j, R2, p2);

        // tracking frame on even joints
        if ((j & 1) == 0) {
            float Rt[9], pt[3];
            mm3(Rt, R2, C + 45);
#pragma unroll
            for (int r = 0; r < 3; r++)
                pt[r] = fmaf(R2[r * 3 + 0], C[54],
                        fmaf(R2[r * 3 + 1], C[55],
                        fmaf(R2[r * 3 + 2], C[56], p2[r])));
            emit_mat(stg, lane, wb0, outTrk, J / 2, j >> 1, Rt, pt);
        }

#pragma unroll
        for (int i = 0; i < 9; i++) R[i] = R2[i];
        p[0] = p2[0]; p[1] = p2[1]; p[2] = p2[2];
    }
}

extern "C" void kernel_launch(void* const* d_in, const int* in_sizes, int n_in,
                              void* d_out, int out_size) {
    const float* rev_q       = (const float*)d_in[0];
    const float* pri_q       = (const float*)d_in[1];
    const float* rev_p_off   = (const float*)d_in[2];
    const float* rev_rpy_off = (const float*)d_in[3];
    const float* pri_p_off   = (const float*)d_in[4];
    const float* pri_rpy_off = (const float*)d_in[5];
    const float* rev_axis    = (const float*)d_in[6];
    const float* pri_axis    = (const float*)d_in[7];
    const float* p_track     = (const float*)d_in[8];
    const float* rpy_track   = (const float*)d_in[9];
    float* out = (float*)d_out;

    int B = in_sizes[0] / J;

    prep_kernel<<<1, 32>>>(rev_p_off, rev_rpy_off, pri_p_off, pri_rpy_off,
                           rev_axis, pri_axis, p_track, rpy_track);

    int grid = (B + 127) / 128;
    fk_kernel<<<grid, 128>>>(rev_q, pri_q, out, B);
}

// round 2
// speedup vs baseline: 1.0566x; 1.0566x over previous
#include <cuda_runtime.h>
#include <math.h>

#define J 20
#define SEG 4
#define JPS 5               // joints per segment
#define CONST_PER_J 57
// per joint: M0[9]@0, M1[9]@9, M2[9]@18, p_rev[3]@27,
//            Rpri[9]@30, v_pri[3]@39, p_pri[3]@42, Rtrk[9]@45, p_trk[3]@54

__device__ __forceinline__ void rpy2r_dev(float r, float p, float y, float* R) {
    float cr = cosf(r), sr = sinf(r);
    float cp = cosf(p), sp = sinf(p);
    float cy = cosf(y), sy = sinf(y);
    R[0] = cy * cp; R[1] = cy * sp * sr - sy * cr; R[2] = cy * sp * cr + sy * sr;
    R[3] = sy * cp; R[4] = sy * sp * sr + cy * cr; R[5] = sy * sp * cr - cy * sr;
    R[6] = -sp;     R[7] = cp * sr;                R[8] = cp * cr;
}

__device__ __forceinline__ void mm3(float* D, const float* A, const float* B) {
#pragma unroll
    for (int r = 0; r < 3; r++)
#pragma unroll
        for (int c = 0; c < 3; c++)
            D[r * 3 + c] = fmaf(A[r * 3 + 0], B[0 * 3 + c],
                           fmaf(A[r * 3 + 1], B[1 * 3 + c],
                                A[r * 3 + 2] * B[2 * 3 + c]));
}

// Stage one 3x4 per lane in warp smem, drain fully coalesced (64B chunks).
__device__ __forceinline__ void emit_mat(float* stg, int lane, int wb0, int B,
                                         float* __restrict__ tbase, int nMat, int slot,
                                         const float* R, const float* p) {
    float4* sp = (float4*)(stg + lane * 12);
    sp[0] = make_float4(R[0], R[1], R[2], p[0]);
    sp[1] = make_float4(R[3], R[4], R[5], p[1]);
    sp[2] = make_float4(R[6], R[7], R[8], p[2]);
    __syncwarp();
#pragma unroll
    for (int k = 0; k < 4; k++) {
        int c  = k * 32 + lane;   // 0..127: 32 rows x 4 quads
        int bl = c >> 2;
        int m  = c & 3;
        float4 v;
        if (m < 3) v = *(const float4*)(stg + bl * 12 + 4 * m);
        else       v = make_float4(0.f, 0.f, 0.f, 1.f);
        int bb = wb0 + bl; if (bb >= B) bb = B - 1;
        *(float4*)(tbase + ((size_t)bb * nMat + slot) * 16 + 4 * m) = v;
    }
    __syncwarp();
}

// Apply joint j: in (R,p) -> out1 (rev) and out2 (pri). Overwrites R,p with out2.
__device__ __forceinline__ void joint_apply(const float* C, float qr, float qp,
                                            float R[9], float p[3],
                                            float R1[9], float p1[3]) {
    float s, c;
    sincosf(qr, &s, &c);
    float ic = 1.f - c;
    float Rs[9];
#pragma unroll
    for (int i = 0; i < 9; i++)
        Rs[i] = fmaf(s, C[9 + i], fmaf(ic, C[18 + i], C[i]));
    mm3(R1, R, Rs);
#pragma unroll
    for (int r = 0; r < 3; r++)
        p1[r] = fmaf(R[r * 3 + 0], C[27],
                fmaf(R[r * 3 + 1], C[28],
                fmaf(R[r * 3 + 2], C[29], p[r])));
    float ps0 = fmaf(qp, C[39], C[42]);
    float ps1 = fmaf(qp, C[40], C[43]);
    float ps2 = fmaf(qp, C[41], C[44]);
    float R2[9];
    mm3(R2, R1, C + 30);
#pragma unroll
    for (int r = 0; r < 3; r++)
        p[r] = fmaf(R1[r * 3 + 0], ps0,
               fmaf(R1[r * 3 + 1], ps1,
               fmaf(R1[r * 3 + 2], ps2, p1[r])));
#pragma unroll
    for (int i = 0; i < 9; i++) R[i] = R2[i];
}

__global__ void __launch_bounds__(128)
fk_kernel(const float* __restrict__ rev_q, const float* __restrict__ pri_q,
          const float* __restrict__ rev_p_off, const float* __restrict__ rev_rpy_off,
          const float* __restrict__ pri_p_off, const float* __restrict__ pri_rpy_off,
          const float* __restrict__ rev_axis, const float* __restrict__ pri_axis,
          const float* __restrict__ p_track, const float* __restrict__ rpy_track,
          float* __restrict__ out, int B) {
    __shared__ float sC[J * CONST_PER_J];
    __shared__ float sQr[32 * 21];         // padded rows: 21 (conflict-free)
    __shared__ float sQp[32 * 21];
    __shared__ float sL[SEG][32 * 13];     // local segment products, padded 13
    __shared__ float sStage[SEG][32 * 12];

    int tid  = threadIdx.x;
    int lane = tid & 31;
    int w    = tid >> 5;                   // segment id
    int b0   = blockIdx.x * 32;

    // ---- per-block constant prep (threads 0..19) ----
    if (tid < J) {
        int j = tid;
        float* C = sC + j * CONST_PER_J;
        float Ro[9];
        rpy2r_dev(rev_rpy_off[j*3+0], rev_rpy_off[j*3+1], rev_rpy_off[j*3+2], Ro);
        float ax = rev_axis[j*3+0], ay = rev_axis[j*3+1], az = rev_axis[j*3+2];
        float n = sqrtf(ax*ax + ay*ay + az*az) + 1e-12f;
        ax /= n; ay /= n; az /= n;
        float K[9]  = {0.f, -az, ay,  az, 0.f, -ax,  -ay, ax, 0.f};
        float K2[9]; mm3(K2, K, K);
        float M1[9], M2[9]; mm3(M1, Ro, K); mm3(M2, Ro, K2);
#pragma unroll
        for (int i = 0; i < 9; i++) { C[i] = Ro[i]; C[9+i] = M1[i]; C[18+i] = M2[i]; }
        C[27] = rev_p_off[j*3+0]; C[28] = rev_p_off[j*3+1]; C[29] = rev_p_off[j*3+2];

        float Rp[9];
        rpy2r_dev(pri_rpy_off[j*3+0], pri_rpy_off[j*3+1], pri_rpy_off[j*3+2], Rp);
#pragma unroll
        for (int i = 0; i < 9; i++) C[30+i] = Rp[i];
        float pax = pri_axis[j*3+0], pay = pri_axis[j*3+1], paz = pri_axis[j*3+2];
#pragma unroll
        for (int r = 0; r < 3; r++)
            C[39+r] = Rp[r*3+0]*pax + Rp[r*3+1]*pay + Rp[r*3+2]*paz;
        C[42] = pri_p_off[j*3+0]; C[43] = pri_p_off[j*3+1]; C[44] = pri_p_off[j*3+2];

        float Rt[9];
        rpy2r_dev(rpy_track[j*3+0], rpy_track[j*3+1], rpy_track[j*3+2], Rt);
#pragma unroll
        for (int i = 0; i < 9; i++) C[45+i] = Rt[i];
        C[54] = p_track[j*3+0]; C[55] = p_track[j*3+1]; C[56] = p_track[j*3+2];
    }

    // ---- stage q for 32 batches (coalesced global reads) ----
    for (int e = tid; e < 32 * J; e += 128) {
        int bb = e / J, jj = e % J;
        int gb = b0 + bb; if (gb >= B) gb = B - 1;
        sQr[bb * 21 + jj] = rev_q[(size_t)gb * J + jj];
        sQp[bb * 21 + jj] = pri_q[(size_t)gb * J + jj];
    }
    __syncthreads();

    const float* qrRow = sQr + lane * 21;
    const float* qpRow = sQp + lane * 21;

    // ---- phase 1: local segment product ----
    float R[9] = {1.f,0.f,0.f, 0.f,1.f,0.f, 0.f,0.f,1.f};
    float p[3] = {0.f, 0.f, 0.f};
#pragma unroll
    for (int i = 0; i < JPS; i++) {
        int j = w * JPS + i;
        const float* C = sC + j * CONST_PER_J;
        float R1[9], p1[3];
        joint_apply(C, qrRow[j], qpRow[j], R, p, R1, p1);
    }
    {
        float* L = sL[w] + lane * 13;
#pragma unroll
        for (int i = 0; i < 9; i++) L[i] = R[i];
        L[9] = p[0]; L[10] = p[1]; L[11] = p[2];
    }
    __syncthreads();

    // ---- phase 2: compose prefix = L0 @ ... @ L_{w-1} ----
    float Rp_[9] = {1.f,0.f,0.f, 0.f,1.f,0.f, 0.f,0.f,1.f};
    float pp_[3] = {0.f, 0.f, 0.f};
    for (int k = 0; k < w; k++) {
        const float* L = sL[k] + lane * 13;
        float Rn[9];
        mm3(Rn, Rp_, L);
        float pn[3];
#pragma unroll
        for (int r = 0; r < 3; r++)
            pn[r] = fmaf(Rp_[r*3+0], L[9],
                    fmaf(Rp_[r*3+1], L[10],
                    fmaf(Rp_[r*3+2], L[11], pp_[r])));
#pragma unroll
        for (int i = 0; i < 9; i++) Rp_[i] = Rn[i];
        pp_[0] = pn[0]; pp_[1] = pn[1]; pp_[2] = pn[2];
    }

    // ---- phase 3: re-run segment from prefix, emitting outputs ----
    float* stg = sStage[w];
    float* outTrk = out;
    float* outRev = out + (size_t)B * 160;   // B*10*16
    float* outPri = out + (size_t)B * 480;   // + B*20*16

#pragma unroll
    for (int i = 0; i < 9; i++) R[i] = Rp_[i];
    p[0] = pp_[0]; p[1] = pp_[1]; p[2] = pp_[2];

#pragma unroll
    for (int i = 0; i < JPS; i++) {
        int j = w * JPS + i;
        const float* C = sC + j * CONST_PER_J;
        float R1[9], p1[3];
        joint_apply(C, qrRow[j], qpRow[j], R, p, R1, p1);
        emit_mat(stg, lane, b0, B, outRev, J, j, R1, p1);
        emit_mat(stg, lane, b0, B, outPri, J, j, R, p);
        if ((j & 1) == 0) {
            float Rt[9], pt[3];
            mm3(Rt, R, C + 45);
#pragma unroll
            for (int r = 0; r < 3; r++)
                pt[r] = fmaf(R[r*3+0], C[54],
                        fmaf(R[r*3+1], C[55],
                        fmaf(R[r*3+2], C[56], p[r])));
            emit_mat(stg, lane, b0, B, outTrk, J / 2, j >> 1, Rt, pt);
        }
    }
}

extern "C" void kernel_launch(void* const* d_in, const int* in_sizes, int n_in,
                              void* d_out, int out_size) {
    const float* rev_q       = (const float*)d_in[0];
    const float* pri_q       = (const float*)d_in[1];
    const float* rev_p_off   = (const float*)d_in[2];
    const float* rev_rpy_off = (const float*)d_in[3];
    const float* pri_p_off   = (const float*)d_in[4];
    const float* pri_rpy_off = (const float*)d_in[5];
    const float* rev_axis    = (const float*)d_in[6];
    const float* pri_axis    = (const float*)d_in[7];
    const float* p_track     = (const float*)d_in[8];
    const float* rpy_track   = (const float*)d_in[9];
    float* out = (float*)d_out;

    int B = in_sizes[0] / J;
    int grid = (B + 31) / 32;
    fk_kernel<<<grid, 128>>>(rev_q, pri_q,
                             rev_p_off, rev_rpy_off, pri_p_off, pri_rpy_off,
                             rev_axis, pri_axis, p_track, rpy_track, out, B);
}

// round 3
// speedup vs baseline: 1.1777x; 1.1146x over previous
#include <cuda_runtime.h>
#include <math.h>

#define J 20
#define JPS 5
#define CONST_PER_J 57
// per joint: M0[9]@0, M1[9]@9, M2[9]@18, p_rev[3]@27,
//            Rpri[9]@30, v_pri[3]@39, p_pri[3]@42, Rtrk[9]@45, p_trk[3]@54

__device__ float g_jc[J * CONST_PER_J];

__device__ __forceinline__ void rpy2r_dev(float r, float p, float y, float* R) {
    float cr = cosf(r), sr = sinf(r);
    float cp = cosf(p), sp = sinf(p);
    float cy = cosf(y), sy = sinf(y);
    R[0] = cy * cp; R[1] = cy * sp * sr - sy * cr; R[2] = cy * sp * cr + sy * sr;
    R[3] = sy * cp; R[4] = sy * sp * sr + cy * cr; R[5] = sy * sp * cr - cy * sr;
    R[6] = -sp;     R[7] = cp * sr;                R[8] = cp * cr;
}

__device__ __forceinline__ void mm3(float* D, const float* A, const float* B) {
#pragma unroll
    for (int r = 0; r < 3; r++)
#pragma unroll
        for (int c = 0; c < 3; c++)
            D[r * 3 + c] = fmaf(A[r * 3 + 0], B[0 * 3 + c],
                           fmaf(A[r * 3 + 1], B[1 * 3 + c],
                                A[r * 3 + 2] * B[2 * 3 + c]));
}

__global__ void prep_kernel(const float* __restrict__ rev_p_off,
                            const float* __restrict__ rev_rpy_off,
                            const float* __restrict__ pri_p_off,
                            const float* __restrict__ pri_rpy_off,
                            const float* __restrict__ rev_axis,
                            const float* __restrict__ pri_axis,
                            const float* __restrict__ p_track,
                            const float* __restrict__ rpy_track) {
    int j = threadIdx.x;
    if (j >= J) return;
    float* C = g_jc + j * CONST_PER_J;
    float Ro[9];
    rpy2r_dev(rev_rpy_off[j*3+0], rev_rpy_off[j*3+1], rev_rpy_off[j*3+2], Ro);
    float ax = rev_axis[j*3+0], ay = rev_axis[j*3+1], az = rev_axis[j*3+2];
    float n = sqrtf(ax*ax + ay*ay + az*az) + 1e-12f;
    ax /= n; ay /= n; az /= n;
    float K[9]  = {0.f, -az, ay,  az, 0.f, -ax,  -ay, ax, 0.f};
    float K2[9]; mm3(K2, K, K);
    float M1[9], M2[9]; mm3(M1, Ro, K); mm3(M2, Ro, K2);
#pragma unroll
    for (int i = 0; i < 9; i++) { C[i] = Ro[i]; C[9+i] = M1[i]; C[18+i] = M2[i]; }
    C[27] = rev_p_off[j*3+0]; C[28] = rev_p_off[j*3+1]; C[29] = rev_p_off[j*3+2];

    float Rp[9];
    rpy2r_dev(pri_rpy_off[j*3+0], pri_rpy_off[j*3+1], pri_rpy_off[j*3+2], Rp);
#pragma unroll
    for (int i = 0; i < 9; i++) C[30+i] = Rp[i];
    float pax = pri_axis[j*3+0], pay = pri_axis[j*3+1], paz = pri_axis[j*3+2];
#pragma unroll
    for (int r = 0; r < 3; r++)
        C[39+r] = Rp[r*3+0]*pax + Rp[r*3+1]*pay + Rp[r*3+2]*paz;
    C[42] = pri_p_off[j*3+0]; C[43] = pri_p_off[j*3+1]; C[44] = pri_p_off[j*3+2];

    float Rt[9];
    rpy2r_dev(rpy_track[j*3+0], rpy_track[j*3+1], rpy_track[j*3+2], Rt);
#pragma unroll
    for (int i = 0; i < 9; i++) C[45+i] = Rt[i];
    C[54] = p_track[j*3+0]; C[55] = p_track[j*3+1]; C[56] = p_track[j*3+2];
}

// joint application with precomputed sin / (1-cos)
__device__ __forceinline__ void joint_apply_c(const float* C, float s, float ic, float qp,
                                              float R[9], float p[3],
                                              float R1[9], float p1[3]) {
    float Rs[9];
#pragma unroll
    for (int i = 0; i < 9; i++)
        Rs[i] = fmaf(s, C[9 + i], fmaf(ic, C[18 + i], C[i]));
    mm3(R1, R, Rs);
#pragma unroll
    for (int r = 0; r < 3; r++)
        p1[r] = fmaf(R[r * 3 + 0], C[27],
                fmaf(R[r * 3 + 1], C[28],
                fmaf(R[r * 3 + 2], C[29], p[r])));
    float ps0 = fmaf(qp, C[39], C[42]);
    float ps1 = fmaf(qp, C[40], C[43]);
    float ps2 = fmaf(qp, C[41], C[44]);
    float R2[9];
    mm3(R2, R1, C + 30);
#pragma unroll
    for (int r = 0; r < 3; r++)
        p[r] = fmaf(R1[r * 3 + 0], ps0,
               fmaf(R1[r * 3 + 1], ps1,
               fmaf(R1[r * 3 + 2], ps2, p1[r])));
#pragma unroll
    for (int i = 0; i < 9; i++) R[i] = R2[i];
}

// All 32 lanes have a matrix (batch=lane>>2, seg=lane&3) for joint 5*seg+i.
__device__ __forceinline__ void emit_full(float* stg, int lane, int i, int wb0, int B,
                                          float* __restrict__ tbase,
                                          const float R[9], const float p[3]) {
    float4* sp = (float4*)(stg + lane * 12);
    sp[0] = make_float4(R[0], R[1], R[2], p[0]);
    sp[1] = make_float4(R[3], R[4], R[5], p[1]);
    sp[2] = make_float4(R[6], R[7], R[8], p[2]);
    __syncwarp();
#pragma unroll
    for (int k = 0; k < 4; k++) {
        int c   = k * 32 + lane;
        int idx = c >> 2;      // source lane 0..31
        int m   = c & 3;
        int bb  = idx >> 2;
        int s2  = idx & 3;
        int gb  = wb0 + bb; if (gb >= B) gb = B - 1;
        int slot = 5 * s2 + i;
        float4 v = (m < 3) ? *(const float4*)(stg + idx * 12 + 4 * m)
                           : make_float4(0.f, 0.f, 0.f, 1.f);
        *(float4*)(tbase + ((size_t)gb * J + slot) * 16 + 4 * m) = v;
    }
    __syncwarp();
}

__device__ __forceinline__ void emit_track(float* stg, int lane, int i, int wb0, int B,
                                           float* __restrict__ tbase,
                                           const float R[9], const float p[3], bool owner) {
    if (owner) {
        float4* sp = (float4*)(stg + lane * 12);
        sp[0] = make_float4(R[0], R[1], R[2], p[0]);
        sp[1] = make_float4(R[3], R[4], R[5], p[1]);
        sp[2] = make_float4(R[6], R[7], R[8], p[2]);
    }
    __syncwarp();
#pragma unroll
    for (int k = 0; k < 2; k++) {
        int c     = k * 32 + lane;   // 0..63
        int idx16 = c >> 2;          // 0..15
        int m     = c & 3;
        int bb    = idx16 >> 1;
        int pos   = idx16 & 1;
        int s2    = (i & 1) + 2 * pos;
        int src   = bb * 4 + s2;
        int slot  = (5 * s2 + i) >> 1;
        int gb    = wb0 + bb; if (gb >= B) gb = B - 1;
        float4 v = (m < 3) ? *(const float4*)(stg + src * 12 + 4 * m)
                           : make_float4(0.f, 0.f, 0.f, 1.f);
        *(float4*)(tbase + ((size_t)gb * (J / 2) + slot) * 16 + 4 * m) = v;
    }
    __syncwarp();
}

__global__ void __launch_bounds__(128, 6)
fk_kernel(const float* __restrict__ rev_q, const float* __restrict__ pri_q,
          float* __restrict__ out, int B) {
    __shared__ float sC[J * CONST_PER_J];
    __shared__ float sStage[4][32 * 12];

    int tid  = threadIdx.x;
    int lane = tid & 31;
    int w    = tid >> 5;
    int bb   = lane >> 2;      // batch within warp group (0..7)
    int s    = lane & 3;       // segment id
    int wb0  = blockIdx.x * 32 + w * 8;
    int gb   = wb0 + bb; if (gb >= B) gb = B - 1;

    // start q loads early (overlap with const staging)
    float qr[JPS], qp[JPS];
#pragma unroll
    for (int i = 0; i < JPS; i++) {
        qr[i] = __ldg(&rev_q[(size_t)gb * J + s * JPS + i]);
        qp[i] = __ldg(&pri_q[(size_t)gb * J + s * JPS + i]);
    }

    for (int i = tid; i < J * CONST_PER_J; i += 128) sC[i] = g_jc[i];
    __syncthreads();

    // ---- phase 1: local segment product, cache trig ----
    float R[9] = {1.f,0.f,0.f, 0.f,1.f,0.f, 0.f,0.f,1.f};
    float p[3] = {0.f, 0.f, 0.f};
    float sn[JPS], ic[JPS];
#pragma unroll
    for (int i = 0; i < JPS; i++) {
        float c;
        sincosf(qr[i], &sn[i], &c);
        ic[i] = 1.f - c;
        const float* C = sC + (s * JPS + i) * CONST_PER_J;
        float R1[9], p1[3];
        joint_apply_c(C, sn[i], ic[i], qp[i], R, p, R1, p1);
    }

    // ---- phase 2: exclusive prefix within 4-lane group via shfl ----
    float P[9] = {1.f,0.f,0.f, 0.f,1.f,0.f, 0.f,0.f,1.f};
    float pp[3] = {0.f, 0.f, 0.f};
    int base = lane & ~3;
#pragma unroll
    for (int k = 0; k < 3; k++) {
        float Lr[9], Lp[3];
#pragma unroll
        for (int t = 0; t < 9; t++) Lr[t] = __shfl_sync(0xffffffffu, R[t], base + k);
#pragma unroll
        for (int t = 0; t < 3; t++) Lp[t] = __shfl_sync(0xffffffffu, p[t], base + k);
        if (k < s) {
            float pn[3];
#pragma unroll
            for (int r = 0; r < 3; r++)
                pn[r] = fmaf(P[r*3+0], Lp[0],
                        fmaf(P[r*3+1], Lp[1],
                        fmaf(P[r*3+2], Lp[2], pp[r])));
            float Rn[9];
            mm3(Rn, P, Lr);
#pragma unroll
            for (int t = 0; t < 9; t++) P[t] = Rn[t];
            pp[0] = pn[0]; pp[1] = pn[1]; pp[2] = pn[2];
        }
    }

    // ---- phase 3: re-run segment from prefix, emitting ----
    float* stg = sStage[w];
    float* outTrk = out;
    float* outRev = out + (size_t)B * 160;
    float* outPri = out + (size_t)B * 480;

#pragma unroll
    for (int t = 0; t < 9; t++) R[t] = P[t];
    p[0] = pp[0]; p[1] = pp[1]; p[2] = pp[2];

#pragma unroll
    for (int i = 0; i < JPS; i++) {
        int j = s * JPS + i;
        const float* C = sC + j * CONST_PER_J;
        float R1[9], p1[3];
        joint_apply_c(C, sn[i], ic[i], qp[i], R, p, R1, p1);
        emit_full(stg, lane, i, wb0, B, outRev, R1, p1);
        emit_full(stg, lane, i, wb0, B, outPri, R, p);

        bool owner = (((s ^ i) & 1) == 0);   // j = 5s+i even <=> s,i same parity
        float Rt[9], pt[3];
        if (owner) {
            mm3(Rt, R, C + 45);
#pragma unroll
            for (int r = 0; r < 3; r++)
                pt[r] = fmaf(R[r*3+0], C[54],
                        fmaf(R[r*3+1], C[55],
                        fmaf(R[r*3+2], C[56], p[r])));
        }
        emit_track(stg, lane, i, wb0, B, outTrk, Rt, pt, owner);
    }
}

extern "C" void kernel_launch(void* const* d_in, const int* in_sizes, int n_in,
                              void* d_out, int out_size) {
    const float* rev_q       = (const float*)d_in[0];
    const float* pri_q       = (const float*)d_in[1];
    const float* rev_p_off   = (const float*)d_in[2];
    const float* rev_rpy_off = (const float*)d_in[3];
    const float* pri_p_off   = (const float*)d_in[4];
    const float* pri_rpy_off = (const float*)d_in[5];
    const float* rev_axis    = (const float*)d_in[6];
    const float* pri_axis    = (const float*)d_in[7];
    const float* p_track     = (const float*)d_in[8];
    const float* rpy_track   = (const float*)d_in[9];
    float* out = (float*)d_out;

    int B = in_sizes[0] / J;

    prep_kernel<<<1, 32>>>(rev_p_off, rev_rpy_off, pri_p_off, pri_rpy_off,
                           rev_axis, pri_axis, p_track, rpy_track);

    int grid = (B + 31) / 32;
    fk_kernel<<<grid, 128>>>(rev_q, pri_q, out, B);
}

// round 4
// speedup vs baseline: 1.4438x; 1.2260x over previous
#include <cuda_runtime.h>
#include <math.h>

#define J 20
#define JPS 5
#define CONST_PER_J 57
// per joint: M0[9]@0, M1[9]@9, M2[9]@18, p_rev[3]@27,
//            Rpri[9]@30, v_pri[3]@39, p_pri[3]@42, Rtrk[9]@45, p_trk[3]@54

__device__ __forceinline__ void rpy2r_fast(float r, float p, float y, float* R) {
    float cr, sr, cp, sp, cy, sy;
    __sincosf(r, &sr, &cr);
    __sincosf(p, &sp, &cp);
    __sincosf(y, &sy, &cy);
    R[0] = cy * cp; R[1] = cy * sp * sr - sy * cr; R[2] = cy * sp * cr + sy * sr;
    R[3] = sy * cp; R[4] = sy * sp * sr + cy * cr; R[5] = sy * sp * cr - cy * sr;
    R[6] = -sp;     R[7] = cp * sr;                R[8] = cp * cr;
}

__device__ __forceinline__ void mm3(float* D, const float* A, const float* B) {
#pragma unroll
    for (int r = 0; r < 3; r++)
#pragma unroll
        for (int c = 0; c < 3; c++)
            D[r * 3 + c] = fmaf(A[r * 3 + 0], B[0 * 3 + c],
                           fmaf(A[r * 3 + 1], B[1 * 3 + c],
                                A[r * 3 + 2] * B[2 * 3 + c]));
}

// joint application with precomputed sin / (1-cos)
__device__ __forceinline__ void joint_apply_c(const float* C, float s, float ic, float qp,
                                              float R[9], float p[3],
                                              float R1[9], float p1[3]) {
    float Rs[9];
#pragma unroll
    for (int i = 0; i < 9; i++)
        Rs[i] = fmaf(s, C[9 + i], fmaf(ic, C[18 + i], C[i]));
    mm3(R1, R, Rs);
#pragma unroll
    for (int r = 0; r < 3; r++)
        p1[r] = fmaf(R[r * 3 + 0], C[27],
                fmaf(R[r * 3 + 1], C[28],
                fmaf(R[r * 3 + 2], C[29], p[r])));
    float ps0 = fmaf(qp, C[39], C[42]);
    float ps1 = fmaf(qp, C[40], C[43]);
    float ps2 = fmaf(qp, C[41], C[44]);
    float R2[9];
    mm3(R2, R1, C + 30);
#pragma unroll
    for (int r = 0; r < 3; r++)
        p[r] = fmaf(R1[r * 3 + 0], ps0,
               fmaf(R1[r * 3 + 1], ps1,
               fmaf(R1[r * 3 + 2], ps2, p1[r])));
#pragma unroll
    for (int i = 0; i < 9; i++) R[i] = R2[i];
}

// All 32 lanes hold a matrix (batch=lane>>2, seg=lane&3) for joint 5*seg+i.
__device__ __forceinline__ void emit_full(float* stg, int lane, int i, int wb0, int B,
                                          float* __restrict__ tbase,
                                          const float R[9], const float p[3]) {
    float4* sp = (float4*)(stg + lane * 12);
    sp[0] = make_float4(R[0], R[1], R[2], p[0]);
    sp[1] = make_float4(R[3], R[4], R[5], p[1]);
    sp[2] = make_float4(R[6], R[7], R[8], p[2]);
    __syncwarp();
#pragma unroll
    for (int k = 0; k < 4; k++) {
        int c   = k * 32 + lane;
        int idx = c >> 2;
        int m   = c & 3;
        int bb  = idx >> 2;
        int s2  = idx & 3;
        int gb  = wb0 + bb; if (gb >= B) gb = B - 1;
        int slot = 5 * s2 + i;
        float4 v = (m < 3) ? *(const float4*)(stg + idx * 12 + 4 * m)
                           : make_float4(0.f, 0.f, 0.f, 1.f);
        *(float4*)(tbase + ((size_t)gb * J + slot) * 16 + 4 * m) = v;
    }
    __syncwarp();
}

__device__ __forceinline__ void emit_track(float* stg, int lane, int i, int wb0, int B,
                                           float* __restrict__ tbase,
                                           const float R[9], const float p[3], bool owner) {
    if (owner) {
        float4* sp = (float4*)(stg + lane * 12);
        sp[0] = make_float4(R[0], R[1], R[2], p[0]);
        sp[1] = make_float4(R[3], R[4], R[5], p[1]);
        sp[2] = make_float4(R[6], R[7], R[8], p[2]);
    }
    __syncwarp();
#pragma unroll
    for (int k = 0; k < 2; k++) {
        int c     = k * 32 + lane;   // 0..63
        int idx16 = c >> 2;          // 0..15
        int m     = c & 3;
        int bb    = idx16 >> 1;
        int pos   = idx16 & 1;
        int s2    = (i & 1) + 2 * pos;
        int src   = bb * 4 + s2;
        int slot  = (5 * s2 + i) >> 1;
        int gb    = wb0 + bb; if (gb >= B) gb = B - 1;
        float4 v = (m < 3) ? *(const float4*)(stg + src * 12 + 4 * m)
                           : make_float4(0.f, 0.f, 0.f, 1.f);
        *(float4*)(tbase + ((size_t)gb * (J / 2) + slot) * 16 + 4 * m) = v;
    }
    __syncwarp();
}

__global__ void __launch_bounds__(128, 7)
fk_kernel(const float* __restrict__ rev_q, const float* __restrict__ pri_q,
          const float* __restrict__ rev_p_off, const float* __restrict__ rev_rpy_off,
          const float* __restrict__ pri_p_off, const float* __restrict__ pri_rpy_off,
          const float* __restrict__ rev_axis, const float* __restrict__ pri_axis,
          const float* __restrict__ p_track, const float* __restrict__ rpy_track,
          float* __restrict__ out, int B) {
    __shared__ float sC[J * CONST_PER_J];
    __shared__ float sStage[4][32 * 12];

    int tid  = threadIdx.x;
    int lane = tid & 31;
    int w    = tid >> 5;
    int bb   = lane >> 2;      // batch within warp group (0..7)
    int s    = lane & 3;       // segment id
    int wb0  = blockIdx.x * 32 + w * 8;
    int gb   = wb0 + bb; if (gb >= B) gb = B - 1;

    // q loads + trig early (overlap with const prep)
    float sn[JPS], ic[JPS], qp[JPS];
#pragma unroll
    for (int i = 0; i < JPS; i++) {
        float q = rev_q[(size_t)gb * J + s * JPS + i];
        float c;
        __sincosf(q, &sn[i], &c);
        ic[i] = 1.f - c;
        qp[i] = pri_q[(size_t)gb * J + s * JPS + i];
    }

    // ---- in-block constant prep (threads 0..19) ----
    if (tid < J) {
        int j = tid;
        float* C = sC + j * CONST_PER_J;
        float Ro[9];
        rpy2r_fast(rev_rpy_off[j*3+0], rev_rpy_off[j*3+1], rev_rpy_off[j*3+2], Ro);
        float ax = rev_axis[j*3+0], ay = rev_axis[j*3+1], az = rev_axis[j*3+2];
        float n = sqrtf(ax*ax + ay*ay + az*az) + 1e-12f;
        ax /= n; ay /= n; az /= n;
        float K[9]  = {0.f, -az, ay,  az, 0.f, -ax,  -ay, ax, 0.f};
        float K2[9]; mm3(K2, K, K);
        float M1[9], M2[9]; mm3(M1, Ro, K); mm3(M2, Ro, K2);
#pragma unroll
        for (int i = 0; i < 9; i++) { C[i] = Ro[i]; C[9+i] = M1[i]; C[18+i] = M2[i]; }
        C[27] = rev_p_off[j*3+0]; C[28] = rev_p_off[j*3+1]; C[29] = rev_p_off[j*3+2];

        float Rp[9];
        rpy2r_fast(pri_rpy_off[j*3+0], pri_rpy_off[j*3+1], pri_rpy_off[j*3+2], Rp);
#pragma unroll
        for (int i = 0; i < 9; i++) C[30+i] = Rp[i];
        float pax = pri_axis[j*3+0], pay = pri_axis[j*3+1], paz = pri_axis[j*3+2];
#pragma unroll
        for (int r = 0; r < 3; r++)
            C[39+r] = Rp[r*3+0]*pax + Rp[r*3+1]*pay + Rp[r*3+2]*paz;
        C[42] = pri_p_off[j*3+0]; C[43] = pri_p_off[j*3+1]; C[44] = pri_p_off[j*3+2];

        float Rt[9];
        rpy2r_fast(rpy_track[j*3+0], rpy_track[j*3+1], rpy_track[j*3+2], Rt);
#pragma unroll
        for (int i = 0; i < 9; i++) C[45+i] = Rt[i];
        C[54] = p_track[j*3+0]; C[55] = p_track[j*3+1]; C[56] = p_track[j*3+2];
    }
    __syncthreads();

    // ---- phase 1: local segment product ----
    float R[9] = {1.f,0.f,0.f, 0.f,1.f,0.f, 0.f,0.f,1.f};
    float p[3] = {0.f, 0.f, 0.f};
#pragma unroll
    for (int i = 0; i < JPS; i++) {
        const float* C = sC + (s * JPS + i) * CONST_PER_J;
        float R1[9], p1[3];
        joint_apply_c(C, sn[i], ic[i], qp[i], R, p, R1, p1);
    }

    // ---- phase 2: exclusive prefix within 4-lane group via shfl ----
    float P[9] = {1.f,0.f,0.f, 0.f,1.f,0.f, 0.f,0.f,1.f};
    float pp[3] = {0.f, 0.f, 0.f};
    int base = lane & ~3;
#pragma unroll
    for (int k = 0; k < 3; k++) {
        float Lr[9], Lp[3];
#pragma unroll
        for (int t = 0; t < 9; t++) Lr[t] = __shfl_sync(0xffffffffu, R[t], base + k);
#pragma unroll
        for (int t = 0; t < 3; t++) Lp[t] = __shfl_sync(0xffffffffu, p[t], base + k);
        if (k < s) {
            float pn[3];
#pragma unroll
            for (int r = 0; r < 3; r++)
                pn[r] = fmaf(P[r*3+0], Lp[0],
                        fmaf(P[r*3+1], Lp[1],
                        fmaf(P[r*3+2], Lp[2], pp[r])));
            float Rn[9];
            mm3(Rn, P, Lr);
#pragma unroll
            for (int t = 0; t < 9; t++) P[t] = Rn[t];
            pp[0] = pn[0]; pp[1] = pn[1]; pp[2] = pn[2];
        }
    }

    // ---- phase 3: re-run segment from prefix, emitting ----
    float* stg = sStage[w];
    float* outTrk = out;
    float* outRev = out + (size_t)B * 160;
    float* outPri = out + (size_t)B * 480;

#pragma unroll
    for (int t = 0; t < 9; t++) R[t] = P[t];
    p[0] = pp[0]; p[1] = pp[1]; p[2] = pp[2];

#pragma unroll
    for (int i = 0; i < JPS; i++) {
        int j = s * JPS + i;
        const float* C = sC + j * CONST_PER_J;
        float R1[9], p1[3];
        joint_apply_c(C, sn[i], ic[i], qp[i], R, p, R1, p1);
        emit_full(stg, lane, i, wb0, B, outRev, R1, p1);
        emit_full(stg, lane, i, wb0, B, outPri, R, p);

        bool owner = (((s ^ i) & 1) == 0);   // j = 5s+i even <=> s,i same parity
        float Rt[9] = {0}, pt[3] = {0};
        if (owner) {
            mm3(Rt, R, C + 45);
#pragma unroll
            for (int r = 0; r < 3; r++)
                pt[r] = fmaf(R[r*3+0], C[54],
                        fmaf(R[r*3+1], C[55],
                        fmaf(R[r*3+2], C[56], p[r])));
        }
        emit_track(stg, lane, i, wb0, B, outTrk, Rt, pt, owner);
    }
}

extern "C" void kernel_launch(void* const* d_in, const int* in_sizes, int n_in,
                              void* d_out, int out_size) {
    const float* rev_q       = (const float*)d_in[0];
    const float* pri_q       = (const float*)d_in[1];
    const float* rev_p_off   = (const float*)d_in[2];
    const float* rev_rpy_off = (const float*)d_in[3];
    const float* pri_p_off   = (const float*)d_in[4];
    const float* pri_rpy_off = (const float*)d_in[5];
    const float* rev_axis    = (const float*)d_in[6];
    const float* pri_axis    = (const float*)d_in[7];
    const float* p_track     = (const float*)d_in[8];
    const float* rpy_track   = (const float*)d_in[9];
    float* out = (float*)d_out;

    int B = in_sizes[0] / J;
    int grid = (B + 31) / 32;
    fk_kernel<<<grid, 128>>>(rev_q, pri_q,
                             rev_p_off, rev_rpy_off, pri_p_off, pri_rpy_off,
                             rev_axis, pri_axis, p_track, rpy_track, out, B);
}